// round 4
// baseline (speedup 1.0000x reference)
#include <cuda_runtime.h>

// Problem constants (from reference setup_inputs)
#define B_TOT 4096
#define N_IN  512
#define N_TOT 2048
#define N_EV  1536
#define N_OUT 256

#define KB    128          // eval nodes per block
#define NBLK  (N_EV / KB)  // 12
#define SUB   16           // triangle sub-block
#define BT    32           // batch columns per CTA
#define NCTA  (B_TOT / BT) // 128
#define NTHR  256          // 8 warps = 2 per SMSP (latency hiding)
#define CH    64           // p-chunk for GEMM staging

#define WSM_PAD   65       // wsm row stride  (65%32==1 -> conflict-free)
#define WSEQ_PAD  129      // wseq row stride (129%32==1)
#define ZS_PAD    36       // zsm row stride
#define ODUP_PAD  68       // dup-o row stride in floats (272B = 17*16 -> LDS.128-aligned)
#define XS_PAD    513      // xsm row stride

// smem layout (floats):
//  U (union region), 16512 floats:
//    init: xsm[32][513]
//    GEMM: wsm[128][65] + osm_dup[64][68]
//    seq : wseq[128][129]
//  zsm[128][36], osm_dupb[128][68], bias[128]
#define U_FLOATS    16512
#define SMEM_FLOATS (U_FLOATS + KB*ZS_PAD + KB*ODUP_PAD + KB)

// Per-CTA-private scratch: outputs, node-major [node][batch].  32 MB.
__device__ float g_outbuf[N_TOT * B_TOT];

typedef unsigned long long ull;

// packed fp32x2 helpers (Blackwell sm_103a: PTX-only, dual-rate FFMA)
__device__ __forceinline__ ull pack2(float lo, float hi) {
    ull r; asm("mov.b64 %0, {%1, %2};" : "=l"(r) : "f"(lo), "f"(hi)); return r;
}
__device__ __forceinline__ float2 unpack2(ull v) {
    float2 r; asm("mov.b64 {%0, %1}, %2;" : "=f"(r.x), "=f"(r.y) : "l"(v)); return r;
}
__device__ __forceinline__ void ffma2(ull& d, ull a, ull b) {
    asm("fma.rn.f32x2 %0, %1, %2, %0;" : "+l"(d) : "l"(a), "l"(b));
}

__device__ __forceinline__ float fast_sigmoid5(float z) {
    float t = fminf(fmaxf(5.0f * z, -60.0f), 60.0f);
    float e;
    asm("ex2.approx.f32 %0, %1;" : "=f"(e) : "f"(-t * 1.4426950408889634f));
    float d = 1.0f + e;
    float o;
    asm("rcp.approx.f32 %0, %1;" : "=f"(o) : "f"(d));
    return o;
}

extern __shared__ float smem[];

__global__ __launch_bounds__(NTHR, 1)
void neat_ff_kernel(const float* __restrict__ x,
                    const float* __restrict__ W,
                    const float* __restrict__ bias,
                    float* __restrict__ out)
{
    float* U        = smem;
    float* zsm      = smem + U_FLOATS;
    float* osm_dupb = zsm + KB * ZS_PAD;
    float* bsm      = osm_dupb + KB * ODUP_PAD;

    const int tid = threadIdx.x;
    const int c0  = blockIdx.x * BT;

    // ---------------- init: transpose this CTA's x slice into g_outbuf ----------
    {
        float* xsm = U;
        for (int idx = tid; idx < BT * N_IN; idx += NTHR) {
            int c = idx / N_IN, p = idx % N_IN;           // coalesced read of x
            xsm[c * XS_PAD + p] = x[(c0 + c) * N_IN + p];
        }
        __syncthreads();
        for (int idx = tid; idx < BT * N_IN; idx += NTHR) {
            int c = idx % BT, p = idx / BT;               // coalesced write (128B rows)
            g_outbuf[p * B_TOT + c0 + c] = xsm[c * XS_PAD + p];
        }
        __syncthreads();
    }

    const int ng  = tid >> 3;   // node group 0..31 (4 nodes each)
    const int cg  = tid & 7;    // col  group 0..7  (4 cols each)
    const int ng4 = ng * 4;

    float* wsm     = U;                  // [KB][WSM_PAD]   node-major W tile
    float* osm_dup = U + KB * WSM_PAD;   // [CH][ODUP_PAD]  duplicated o pairs

    for (int t = 0; t < NBLK; ++t) {
        const int start = N_IN + t * KB;   // first global column of this block
        const int erow0 = t * KB;          // first eval row in W / bias

        // acc2[i][c]: node pair (ng4+2i, ng4+2i+1), col cg*4+c
        ull acc2[2][4];
        #pragma unroll
        for (int i = 0; i < 2; ++i)
            #pragma unroll
            for (int c = 0; c < 4; ++c) acc2[i][c] = 0ull;

        if (tid < KB) bsm[tid] = bias[erow0 + tid];  // visible after first chunk barrier

        // -------- GEMM: acc += W[block, 0:start] * out[0:start, cols] ----------
        for (int p0 = 0; p0 < start; p0 += CH) {
            __syncthreads();  // protect prior users of U, order g_outbuf writes
            for (int idx = tid; idx < KB * CH; idx += NTHR) {
                int n = idx / CH, j = idx % CH;           // coalesced 256B row reads
                wsm[n * WSM_PAD + j] = W[(erow0 + n) * N_TOT + p0 + j];
            }
            for (int idx = tid; idx < CH * BT; idx += NTHR) {
                int j = idx / BT, c = idx % BT;           // coalesced 128B rows
                float v = g_outbuf[(p0 + j) * B_TOT + c0 + c];
                *(float2*)&osm_dup[j * ODUP_PAD + 2 * c] = make_float2(v, v);
            }
            __syncthreads();

            #pragma unroll 4
            for (int p = 0; p < CH; ++p) {
                float w0 = wsm[(ng4 + 0) * WSM_PAD + p];
                float w1 = wsm[(ng4 + 1) * WSM_PAD + p];
                float w2 = wsm[(ng4 + 2) * WSM_PAD + p];
                float w3 = wsm[(ng4 + 3) * WSM_PAD + p];
                ull wp0 = pack2(w0, w1), wp1 = pack2(w2, w3);
                const ull* od = (const ull*)&osm_dup[p * ODUP_PAD + cg * 8];
                ull o0 = od[0], o1 = od[1], o2 = od[2], o3 = od[3];
                ffma2(acc2[0][0], wp0, o0); ffma2(acc2[1][0], wp1, o0);
                ffma2(acc2[0][1], wp0, o1); ffma2(acc2[1][1], wp1, o1);
                ffma2(acc2[0][2], wp0, o2); ffma2(acc2[1][2], wp1, o2);
                ffma2(acc2[0][3], wp0, o3); ffma2(acc2[1][3], wp1, o3);
            }
        }
        __syncthreads();

        // -------- stage within-block W tile: [128 rows][start .. start+127] ----
        float* wseq = U;
        for (int idx = tid; idx < KB * KB; idx += NTHR) {
            int n = idx / KB, j = idx % KB;               // coalesced 512B rows
            wseq[n * WSEQ_PAD + j] = W[(erow0 + n) * N_TOT + start + j];
        }
        __syncthreads();

        // -------- hierarchical sequential solve: 8 x (16-triangle + rank-16) ---
        for (int s = 0; s < 8; ++s) {
            // owners of this sub-block dump their current z into zsm
            if ((ng >> 2) == s) {
                #pragma unroll
                for (int i = 0; i < 2; ++i)
                    #pragma unroll
                    for (int c = 0; c < 4; ++c) {
                        float2 v = unpack2(acc2[i][c]);
                        zsm[(ng4 + 2 * i)     * ZS_PAD + cg * 4 + c] = v.x;
                        zsm[(ng4 + 2 * i + 1) * ZS_PAD + cg * 4 + c] = v.y;
                    }
            }
            __syncthreads();

            // 16-step triangle solve, one thread per batch column
            if (tid < BT) {
                const int col  = tid;
                const int base = s * SUB;
                float oreg[SUB];
                #pragma unroll
                for (int i = 0; i < SUB; ++i) {
                    float z = zsm[(base + i) * ZS_PAD + col] + bsm[base + i];
                    #pragma unroll
                    for (int j = 0; j < i; ++j)
                        z += wseq[(base + i) * WSEQ_PAD + (base + j)] * oreg[j];
                    float o = fast_sigmoid5(z);
                    oreg[i] = o;
                    *(float2*)&osm_dupb[(base + i) * ODUP_PAD + 2 * col] = make_float2(o, o);
                }
            }
            __syncthreads();

            // rank-16 update of all later nodes in the block (packed f32x2)
            if (ng >= 4 * (s + 1)) {
                #pragma unroll
                for (int j = 0; j < SUB; ++j) {
                    int jj = s * SUB + j;
                    float w0 = wseq[(ng4 + 0) * WSEQ_PAD + jj];
                    float w1 = wseq[(ng4 + 1) * WSEQ_PAD + jj];
                    float w2 = wseq[(ng4 + 2) * WSEQ_PAD + jj];
                    float w3 = wseq[(ng4 + 3) * WSEQ_PAD + jj];
                    ull wp0 = pack2(w0, w1), wp1 = pack2(w2, w3);
                    const ull* od = (const ull*)&osm_dupb[jj * ODUP_PAD + cg * 8];
                    ull o0 = od[0], o1 = od[1], o2 = od[2], o3 = od[3];
                    ffma2(acc2[0][0], wp0, o0); ffma2(acc2[1][0], wp1, o0);
                    ffma2(acc2[0][1], wp0, o1); ffma2(acc2[1][1], wp1, o1);
                    ffma2(acc2[0][2], wp0, o2); ffma2(acc2[1][2], wp1, o2);
                    ffma2(acc2[0][3], wp0, o3); ffma2(acc2[1][3], wp1, o3);
                }
            }
        }
        __syncthreads();

        // -------- commit block outputs to scratch (and final output) -----------
        for (int idx = tid; idx < KB * BT; idx += NTHR) {
            int c = idx % BT, j = idx / BT;               // coalesced 128B rows
            g_outbuf[(start + j) * B_TOT + c0 + c] = osm_dupb[j * ODUP_PAD + 2 * c];
        }
        if (start >= N_TOT - N_OUT) {
            const int off = start - (N_TOT - N_OUT);
            for (int idx = tid; idx < KB * BT; idx += NTHR) {
                int j = idx % KB, c = idx / KB;           // coalesced along node dim
                out[(c0 + c) * N_OUT + off + j] = osm_dupb[j * ODUP_PAD + 2 * c];
            }
        }
        // next iteration's first chunk barrier orders these writes before reads
    }
}

extern "C" void kernel_launch(void* const* d_in, const int* in_sizes, int n_in,
                              void* d_out, int out_size)
{
    const float* x    = (const float*)d_in[0];
    const float* W    = (const float*)d_in[1];
    const float* bias = (const float*)d_in[2];
    float* out        = (float*)d_out;

    const int smem_bytes = SMEM_FLOATS * (int)sizeof(float);
    cudaFuncSetAttribute(neat_ff_kernel,
                         cudaFuncAttributeMaxDynamicSharedMemorySize, smem_bytes);
    neat_ff_kernel<<<NCTA, NTHR, smem_bytes>>>(x, W, bias, out);
}

// round 5
// speedup vs baseline: 2.0414x; 2.0414x over previous
#include <cuda_runtime.h>

// Problem constants (from reference setup_inputs)
#define B_TOT 4096
#define N_IN  512
#define N_TOT 2048
#define N_EV  1536
#define N_OUT 256

#define KB    128          // eval nodes per block
#define NBLK  (N_EV / KB)  // 12
#define SUB   16           // triangle sub-block
#define BT    32           // batch columns per CTA
#define NCTA  (B_TOT / BT) // 128
#define NTHR  256          // 8 warps = 2 per SMSP
#define CH    128          // p-chunk for GEMM staging (starts are multiples of 128)

#define WSM_PAD   132      // wsm row stride, floats (16B-aligned rows)
#define WSEQ_PAD  129      // wseq row stride (129%32==1 -> broadcast-friendly)
#define OS_PAD    36       // osm / zsm / osm_blk row stride (16B-aligned, 36%32=4)
#define XS_PAD    513      // xsm row stride

// smem layout (floats):
//  U (union region), 21504 floats:
//    init: xsm[32][513]                     (16416)
//    GEMM: wsm[128][132] + osm[128][36]     (16896 + 4608 = 21504)
//    seq : wseq[128][129]                   (16512)
//  zsm[128][36], osm_blk[128][36], bias[128]
#define U_FLOATS    21504
#define SMEM_FLOATS (U_FLOATS + KB*OS_PAD + KB*OS_PAD + KB)

// Per-CTA-private scratch: outputs, node-major [node][batch].  32 MB.
__device__ float g_outbuf[N_TOT * B_TOT];

typedef unsigned long long ull;

// packed fp32x2 helpers (Blackwell sm_103a: PTX-only)
__device__ __forceinline__ ull pack2(float lo, float hi) {
    ull r; asm("mov.b64 %0, {%1, %2};" : "=l"(r) : "f"(lo), "f"(hi)); return r;
}
__device__ __forceinline__ float2 unpack2(ull v) {
    float2 r; asm("mov.b64 {%0, %1}, %2;" : "=f"(r.x), "=f"(r.y) : "l"(v)); return r;
}
__device__ __forceinline__ void ffma2(ull& d, ull a, ull b) {
    asm("fma.rn.f32x2 %0, %1, %2, %0;" : "+l"(d) : "l"(a), "l"(b));
}

__device__ __forceinline__ float fast_sigmoid5(float z) {
    float t = fminf(fmaxf(5.0f * z, -60.0f), 60.0f);
    float e;
    asm("ex2.approx.f32 %0, %1;" : "=f"(e) : "f"(-t * 1.4426950408889634f));
    float d = 1.0f + e;
    float o;
    asm("rcp.approx.f32 %0, %1;" : "=f"(o) : "f"(d));
    return o;
}

extern __shared__ float smem[];

// one q-step of the GEMM micro-kernel: 4 nodes x 4 cols, col-packed
#define GEMM_STEP(Q, COMP)                                                   \
    {                                                                        \
        const ull* o2 = (const ull*)&osm[(p + Q) * OS_PAD + cg * 4];         \
        ull o0 = o2[0], o1 = o2[1];                                          \
        ull wp;                                                              \
        wp = pack2(w4[0].COMP, w4[0].COMP);                                  \
        ffma2(acc2[0][0], wp, o0); ffma2(acc2[0][1], wp, o1);                \
        wp = pack2(w4[1].COMP, w4[1].COMP);                                  \
        ffma2(acc2[1][0], wp, o0); ffma2(acc2[1][1], wp, o1);                \
        wp = pack2(w4[2].COMP, w4[2].COMP);                                  \
        ffma2(acc2[2][0], wp, o0); ffma2(acc2[2][1], wp, o1);                \
        wp = pack2(w4[3].COMP, w4[3].COMP);                                  \
        ffma2(acc2[3][0], wp, o0); ffma2(acc2[3][1], wp, o1);                \
    }

__global__ __launch_bounds__(NTHR, 1)
void neat_ff_kernel(const float* __restrict__ x,
                    const float* __restrict__ W,
                    const float* __restrict__ bias,
                    float* __restrict__ out)
{
    float* U       = smem;
    float* zsm     = smem + U_FLOATS;
    float* osm_blk = zsm + KB * OS_PAD;
    float* bsm     = osm_blk + KB * OS_PAD;

    const int tid = threadIdx.x;
    const int c0  = blockIdx.x * BT;

    // ---------------- init: transpose this CTA's x slice into g_outbuf ----------
    {
        float* xsm = U;
        for (int idx = tid; idx < BT * N_IN; idx += NTHR) {
            int c = idx / N_IN, p = idx % N_IN;           // coalesced read of x
            xsm[c * XS_PAD + p] = x[(c0 + c) * N_IN + p];
        }
        __syncthreads();
        for (int idx = tid; idx < BT * N_IN; idx += NTHR) {
            int c = idx % BT, p = idx / BT;               // coalesced write (128B rows)
            g_outbuf[p * B_TOT + c0 + c] = xsm[c * XS_PAD + p];
        }
        __syncthreads();
    }

    const int ng  = tid >> 3;   // node group 0..31 (4 nodes each)
    const int cg  = tid & 7;    // col  group 0..7  (4 cols each)
    const int ng4 = ng * 4;

    float* wsm = U;                  // [KB][WSM_PAD]  node-major W tile
    float* osm = U + KB * WSM_PAD;   // [CH][OS_PAD]   natural o (no dup)

    for (int t = 0; t < NBLK; ++t) {
        const int start = N_IN + t * KB;   // first global column of this block
        const int erow0 = t * KB;          // first eval row in W / bias

        // acc2[k][h]: node ng4+k, col pair (cg*4+2h, cg*4+2h+1)
        ull acc2[4][2];
        #pragma unroll
        for (int k = 0; k < 4; ++k) { acc2[k][0] = 0ull; acc2[k][1] = 0ull; }

        if (tid < KB) bsm[tid] = bias[erow0 + tid];  // visible after first chunk barrier

        // -------- GEMM: acc += W[block, 0:start] * out[0:start, cols] ----------
        for (int p0 = 0; p0 < start; p0 += CH) {
            __syncthreads();  // protect prior users of U, order g_outbuf writes
            // stage W tile [128 nodes][128 p] via float4 (16 per thread)
            for (int idx = tid; idx < KB * (CH / 4); idx += NTHR) {
                int n = idx >> 5, j4 = idx & 31;
                float4 v = ((const float4*)(W + (size_t)(erow0 + n) * N_TOT + p0))[j4];
                *(float4*)&wsm[n * WSM_PAD + j4 * 4] = v;
            }
            // stage o tile [128 p][32 c] natural
            for (int idx = tid; idx < CH * BT; idx += NTHR) {
                int p = idx >> 5, c = idx & 31;
                osm[p * OS_PAD + c] = g_outbuf[(size_t)(p0 + p) * B_TOT + c0 + c];
            }
            __syncthreads();

            #pragma unroll 2
            for (int p = 0; p < CH; p += 4) {
                float4 w4[4];
                #pragma unroll
                for (int k = 0; k < 4; ++k)
                    w4[k] = *(const float4*)&wsm[(ng4 + k) * WSM_PAD + p];
                GEMM_STEP(0, x)
                GEMM_STEP(1, y)
                GEMM_STEP(2, z)
                GEMM_STEP(3, w)
            }
        }
        __syncthreads();

        // -------- stage within-block W tile: [128 rows][start .. start+127] ----
        float* wseq = U;
        for (int idx = tid; idx < KB * KB; idx += NTHR) {
            int n = idx / KB, j = idx % KB;               // coalesced 512B rows
            wseq[n * WSEQ_PAD + j] = W[(size_t)(erow0 + n) * N_TOT + start + j];
        }
        __syncthreads();

        // -------- hierarchical sequential solve: 8 x (16-triangle + rank-16) ---
        for (int s = 0; s < 8; ++s) {
            // owners of this sub-block dump their current z into zsm
            if ((ng >> 2) == s) {
                #pragma unroll
                for (int k = 0; k < 4; ++k)
                    #pragma unroll
                    for (int h = 0; h < 2; ++h) {
                        float2 v = unpack2(acc2[k][h]);
                        zsm[(ng4 + k) * OS_PAD + cg * 4 + 2 * h]     = v.x;
                        zsm[(ng4 + k) * OS_PAD + cg * 4 + 2 * h + 1] = v.y;
                    }
            }
            __syncthreads();

            // 16-step triangle solve, one thread per batch column
            if (tid < BT) {
                const int col  = tid;
                const int base = s * SUB;
                float oreg[SUB];
                #pragma unroll
                for (int i = 0; i < SUB; ++i) {
                    float z = zsm[(base + i) * OS_PAD + col] + bsm[base + i];
                    #pragma unroll
                    for (int j = 0; j < i; ++j)
                        z += wseq[(base + i) * WSEQ_PAD + (base + j)] * oreg[j];
                    float o = fast_sigmoid5(z);
                    oreg[i] = o;
                    osm_blk[(base + i) * OS_PAD + col] = o;
                }
            }
            __syncthreads();

            // rank-16 update of all later nodes in the block (col-packed f32x2)
            if (ng >= 4 * (s + 1)) {
                #pragma unroll
                for (int j = 0; j < SUB; ++j) {
                    int jj = s * SUB + j;
                    const ull* o2 = (const ull*)&osm_blk[jj * OS_PAD + cg * 4];
                    ull o0 = o2[0], o1 = o2[1];
                    #pragma unroll
                    for (int k = 0; k < 4; ++k) {
                        float w = wseq[(ng4 + k) * WSEQ_PAD + jj];
                        ull wp = pack2(w, w);
                        ffma2(acc2[k][0], wp, o0);
                        ffma2(acc2[k][1], wp, o1);
                    }
                }
            }
        }
        __syncthreads();

        // -------- commit block outputs to scratch (and final output) -----------
        for (int idx = tid; idx < KB * BT; idx += NTHR) {
            int c = idx & 31, j = idx >> 5;               // coalesced 128B rows
            g_outbuf[(size_t)(start + j) * B_TOT + c0 + c] = osm_blk[j * OS_PAD + c];
        }
        if (start >= N_TOT - N_OUT) {
            const int off = start - (N_TOT - N_OUT);
            for (int idx = tid; idx < KB * BT; idx += NTHR) {
                int j = idx % KB, c = idx / KB;           // coalesced along node dim
                out[(c0 + c) * N_OUT + off + j] = osm_blk[j * OS_PAD + c];
            }
        }
        // next iteration's first chunk barrier orders these writes before reads
    }
}

extern "C" void kernel_launch(void* const* d_in, const int* in_sizes, int n_in,
                              void* d_out, int out_size)
{
    const float* x    = (const float*)d_in[0];
    const float* W    = (const float*)d_in[1];
    const float* bias = (const float*)d_in[2];
    float* out        = (float*)d_out;

    const int smem_bytes = SMEM_FLOATS * (int)sizeof(float);
    cudaFuncSetAttribute(neat_ff_kernel,
                         cudaFuncAttributeMaxDynamicSharedMemorySize, smem_bytes);
    neat_ff_kernel<<<NCTA, NTHR, smem_bytes>>>(x, W, bias, out);
}

// round 7
// speedup vs baseline: 3.5583x; 1.7430x over previous
#include <cuda_runtime.h>
#include <cuda_bf16.h>

#define B_TOT 4096
#define N_IN  512
#define N_TOT 2048
#define N_EV  1536
#define N_OUT 256

#define KB    128          // eval nodes per block (GEMM M)
#define NBLK  (N_EV / KB)  // 12
#define SUB   16           // triangle sub-block
#define BT    32           // batch columns per CTA (GEMM N)
#define NCTA  (B_TOT / BT) // 128
#define NTHR  256          // 8 warps
#define CH    128          // K-chunk

#define OS_PAD   36
#define WSEQ_PAD 129
#define WT_STRIDE 272      // bytes per bf16 tile row (17 x 16B -> conflict-free)

// smem byte offsets
#define W_HI  0                       // 128 x 272 = 34816
#define W_LO  34816
#define O_HI  69632                   // 32 x 272 = 8704
#define O_LO  78336
// union region size 87040 (also holds wseq fp32 [128][129] = 66048)
#define ZSM_OFF 87040                 // float [128][36] = 18432
#define OSB_OFF (ZSM_OFF + 18432)
#define BSM_OFF (OSB_OFF + 18432)
#define SMEM_BYTES (BSM_OFF + 512)    // 124416

// global bf16 hi/lo tensors (pre-pass W; running outputs in [batch][node])
__device__ __nv_bfloat16 g_Whi[(size_t)N_EV * N_TOT];
__device__ __nv_bfloat16 g_Wlo[(size_t)N_EV * N_TOT];
__device__ __nv_bfloat16 g_ohi[(size_t)B_TOT * N_TOT];
__device__ __nv_bfloat16 g_olo[(size_t)B_TOT * N_TOT];

typedef unsigned long long ull;
typedef unsigned int uint;
typedef unsigned short ushort;

__device__ __forceinline__ uint smem_u32_of(const void* p) {
    uint a; asm("{ .reg .u64 t; cvta.to.shared.u64 t, %1; cvt.u32.u64 %0, t; }"
                : "=r"(a) : "l"(p)); return a;
}
__device__ __forceinline__ void ldsm_x4(uint* r, uint a) {
    asm volatile("ldmatrix.sync.aligned.m8n8.x4.shared.b16 {%0,%1,%2,%3}, [%4];"
                 : "=r"(r[0]), "=r"(r[1]), "=r"(r[2]), "=r"(r[3]) : "r"(a));
}
__device__ __forceinline__ void mma16816(float* d, const uint* a, const uint* b) {
    asm volatile("mma.sync.aligned.m16n8k16.row.col.f32.bf16.bf16.f32 "
                 "{%0,%1,%2,%3}, {%4,%5,%6,%7}, {%8,%9}, {%0,%1,%2,%3};"
                 : "+f"(d[0]), "+f"(d[1]), "+f"(d[2]), "+f"(d[3])
                 : "r"(a[0]), "r"(a[1]), "r"(a[2]), "r"(a[3]),
                   "r"(b[0]), "r"(b[1]));
}

// packed fp32x2 (solve phase)
__device__ __forceinline__ ull pack2(float lo, float hi) {
    ull r; asm("mov.b64 %0, {%1, %2};" : "=l"(r) : "f"(lo), "f"(hi)); return r;
}
__device__ __forceinline__ float2 unpack2(ull v) {
    float2 r; asm("mov.b64 {%0, %1}, %2;" : "=f"(r.x), "=f"(r.y) : "l"(v)); return r;
}
__device__ __forceinline__ void ffma2(ull& d, ull a, ull b) {
    asm("fma.rn.f32x2 %0, %1, %2, %0;" : "+l"(d) : "l"(a), "l"(b));
}
__device__ __forceinline__ float fast_sigmoid5(float z) {
    float t = fminf(fmaxf(5.0f * z, -60.0f), 60.0f);
    float e; asm("ex2.approx.f32 %0, %1;" : "=f"(e) : "f"(-t * 1.4426950408889634f));
    float d = 1.0f + e;
    float o; asm("rcp.approx.f32 %0, %1;" : "=f"(o) : "f"(d));
    return o;
}
__device__ __forceinline__ void split_bf16(float v, ushort& h, ushort& l) {
    __nv_bfloat16 hb = __float2bfloat16_rn(v);
    __nv_bfloat16 lb = __float2bfloat16_rn(v - __bfloat162float(hb));
    h = __bfloat16_as_ushort(hb);
    l = __bfloat16_as_ushort(lb);
}

// ---------------- pre-pass: W fp32 -> bf16 hi/lo ----------------
__global__ void convW_kernel(const float* __restrict__ W) {
    int i = blockIdx.x * 256 + threadIdx.x;        // float4 index
    float4 v = ((const float4*)W)[i];
    ushort h0, h1, h2, h3, l0, l1, l2, l3;
    split_bf16(v.x, h0, l0); split_bf16(v.y, h1, l1);
    split_bf16(v.z, h2, l2); split_bf16(v.w, h3, l3);
    uint2 hp = make_uint2(((uint)h1 << 16) | h0, ((uint)h3 << 16) | h2);
    uint2 lp = make_uint2(((uint)l1 << 16) | l0, ((uint)l3 << 16) | l2);
    ((uint2*)g_Whi)[i] = hp;
    ((uint2*)g_Wlo)[i] = lp;
}

extern __shared__ char smemc[];

__global__ __launch_bounds__(NTHR, 1)
void neat_ff_kernel(const float* __restrict__ x,
                    const float* __restrict__ W,
                    const float* __restrict__ bias,
                    float* __restrict__ out)
{
    float* zsm     = (float*)(smemc + ZSM_OFF);
    float* osm_blk = (float*)(smemc + OSB_OFF);
    float* bsm     = (float*)(smemc + BSM_OFF);

    const int  tid = threadIdx.x;
    const int  wid = tid >> 5;
    const int  lid = tid & 31;
    const int  c0  = blockIdx.x * BT;
    const uint smem_base = smem_u32_of(smemc);

    // ---- init: x rows -> g_ohi/g_olo (contiguous, no transpose) ----
    for (int idx = tid; idx < BT * (N_IN / 4); idx += NTHR) {
        int c = idx >> 7, j4 = idx & 127;
        float4 v = *(const float4*)(x + (size_t)(c0 + c) * N_IN + j4 * 4);
        ushort h0, h1, h2, h3, l0, l1, l2, l3;
        split_bf16(v.x, h0, l0); split_bf16(v.y, h1, l1);
        split_bf16(v.z, h2, l2); split_bf16(v.w, h3, l3);
        size_t g = (size_t)(c0 + c) * N_TOT + j4 * 4;
        *(uint2*)(g_ohi + g) = make_uint2(((uint)h1 << 16) | h0, ((uint)h3 << 16) | h2);
        *(uint2*)(g_olo + g) = make_uint2(((uint)l1 << 16) | l0, ((uint)l3 << 16) | l2);
    }

    // per-thread fragment addresses (within tile, byte offsets)
    const int r0 = wid * 16;                                  // warp's 16 M-rows
    const uint aA = smem_base + (uint)(r0 + (lid & 15)) * WT_STRIDE + (uint)(lid >> 4) * 16;
    const int  bg = lid >> 3;                                 // 0..3
    const uint aB = smem_base + (uint)(((bg >> 1) * 8) + (lid & 7)) * WT_STRIDE + (uint)(bg & 1) * 16;

    const int ng  = tid >> 3;   // 0..31 node groups of 4 (solve phase)
    const int cg  = tid & 7;    // 0..7  col groups of 4
    const int ng4 = ng * 4;

    for (int t = 0; t < NBLK; ++t) {
        const int start = N_IN + t * KB;
        const int erow0 = t * KB;

        if (tid < KB) bsm[tid] = bias[erow0 + tid];

        // ================= HMMA GEMM over previous outputs =================
        float d[4][4];
        #pragma unroll
        for (int nt = 0; nt < 4; ++nt)
            #pragma unroll
            for (int k = 0; k < 4; ++k) d[nt][k] = 0.0f;

        const int nchunk = start / CH;
        for (int ci = 0; ci < nchunk; ++ci) {
            const int p0 = ci * CH;
            __syncthreads();   // tiles free; orders g_ohi/g_olo commits

            // stage W hi/lo tiles: [128 rows][128 k] bf16 (pure copy)
            for (int idx = tid; idx < KB * 16; idx += NTHR) {
                int n = idx >> 4, j8 = idx & 15;
                size_t g = (size_t)(erow0 + n) * N_TOT + p0 + j8 * 8;
                *(uint4*)(smemc + W_HI + n * WT_STRIDE + j8 * 16) = *(const uint4*)(g_Whi + g);
                *(uint4*)(smemc + W_LO + n * WT_STRIDE + j8 * 16) = *(const uint4*)(g_Wlo + g);
            }
            // stage o hi/lo tiles: [32 n][128 k] bf16
            for (int idx = tid; idx < BT * 16; idx += NTHR) {
                int n = idx >> 4, j8 = idx & 15;
                size_t g = (size_t)(c0 + n) * N_TOT + p0 + j8 * 8;
                *(uint4*)(smemc + O_HI + n * WT_STRIDE + j8 * 16) = *(const uint4*)(g_ohi + g);
                *(uint4*)(smemc + O_LO + n * WT_STRIDE + j8 * 16) = *(const uint4*)(g_olo + g);
            }
            __syncthreads();

            #pragma unroll
            for (int kk = 0; kk < 8; ++kk) {
                const uint ko = (uint)kk * 32;
                uint Ah[4], Al[4], Bh0[4], Bh1[4], Bl0[4], Bl1[4];
                ldsm_x4(Ah, aA + W_HI + ko);
                ldsm_x4(Al, aA + W_LO + ko);
                ldsm_x4(Bh0, aB + O_HI + ko);                      // n 0..15
                ldsm_x4(Bh1, aB + O_HI + 16 * WT_STRIDE + ko);     // n 16..31
                ldsm_x4(Bl0, aB + O_LO + ko);
                ldsm_x4(Bl1, aB + O_LO + 16 * WT_STRIDE + ko);
                // 3-pass split: Wh*oh + Wl*oh + Wh*ol
                mma16816(d[0], Ah, Bh0 + 0);  mma16816(d[1], Ah, Bh0 + 2);
                mma16816(d[2], Ah, Bh1 + 0);  mma16816(d[3], Ah, Bh1 + 2);
                mma16816(d[0], Al, Bh0 + 0);  mma16816(d[1], Al, Bh0 + 2);
                mma16816(d[2], Al, Bh1 + 0);  mma16816(d[3], Al, Bh1 + 2);
                mma16816(d[0], Ah, Bl0 + 0);  mma16816(d[1], Ah, Bl0 + 2);
                mma16816(d[2], Ah, Bl1 + 0);  mma16816(d[3], Ah, Bl1 + 2);
            }
        }

        // ---- write fragments (z pre-bias) into zsm ----
        {
            int rl = r0 + (lid >> 2), cb = (lid & 3) * 2;
            #pragma unroll
            for (int nt = 0; nt < 4; ++nt) {
                *(float2*)&zsm[rl * OS_PAD + nt * 8 + cb]       = make_float2(d[nt][0], d[nt][1]);
                *(float2*)&zsm[(rl + 8) * OS_PAD + nt * 8 + cb] = make_float2(d[nt][2], d[nt][3]);
            }
        }
        __syncthreads();

        // ---- stage in-block fp32 W tile (reuses union region) ----
        float* wseq = (float*)smemc;
        for (int idx = tid; idx < KB * KB; idx += NTHR) {
            int n = idx / KB, j = idx % KB;
            wseq[n * WSEQ_PAD + j] = W[(size_t)(erow0 + n) * N_TOT + start + j];
        }
        __syncthreads();

        // ---- load this thread's z tile into packed registers ----
        ull acc2[4][2];
        #pragma unroll
        for (int k = 0; k < 4; ++k) {
            const float* zr = zsm + (ng4 + k) * OS_PAD + cg * 4;
            acc2[k][0] = pack2(zr[0], zr[1]);
            acc2[k][1] = pack2(zr[2], zr[3]);
        }

        // ---- hierarchical sequential solve: 8 x (16-triangle + rank-16) ----
        for (int s = 0; s < 8; ++s) {
            if ((ng >> 2) == s) {
                #pragma unroll
                for (int k = 0; k < 4; ++k)
                    #pragma unroll
                    for (int h = 0; h < 2; ++h) {
                        float2 v = unpack2(acc2[k][h]);
                        zsm[(ng4 + k) * OS_PAD + cg * 4 + 2 * h]     = v.x;
                        zsm[(ng4 + k) * OS_PAD + cg * 4 + 2 * h + 1] = v.y;
                    }
            }
            __syncthreads();

            if (tid < BT) {
                const int col  = tid;
                const int base = s * SUB;
                float oreg[SUB];
                #pragma unroll
                for (int i = 0; i < SUB; ++i) {
                    float z = zsm[(base + i) * OS_PAD + col] + bsm[base + i];
                    #pragma unroll
                    for (int j = 0; j < i; ++j)
                        z += wseq[(base + i) * WSEQ_PAD + (base + j)] * oreg[j];
                    float o = fast_sigmoid5(z);
                    oreg[i] = o;
                    osm_blk[(base + i) * OS_PAD + col] = o;
                }
            }
            __syncthreads();

            if (ng >= 4 * (s + 1)) {
                #pragma unroll
                for (int j = 0; j < SUB; ++j) {
                    int jj = s * SUB + j;
                    const ull* o2 = (const ull*)&osm_blk[jj * OS_PAD + cg * 4];
                    ull o0 = o2[0], o1 = o2[1];
                    #pragma unroll
                    for (int k = 0; k < 4; ++k) {
                        float w = wseq[(ng4 + k) * WSEQ_PAD + jj];
                        ull wp = pack2(w, w);
                        ffma2(acc2[k][0], wp, o0);
                        ffma2(acc2[k][1], wp, o1);
                    }
                }
            }
        }
        __syncthreads();

        // ---- commit block outputs as bf16 hi/lo ([batch][node] layout) ----
        for (int idx = tid; idx < BT * (KB / 2); idx += NTHR) {
            int c = idx >> 6, j2 = idx & 63;
            float o0 = osm_blk[(2 * j2) * OS_PAD + c];
            float o1 = osm_blk[(2 * j2 + 1) * OS_PAD + c];
            ushort h0, h1, l0, l1;
            split_bf16(o0, h0, l0);
            split_bf16(o1, h1, l1);
            size_t g = (size_t)(c0 + c) * N_TOT + start + 2 * j2;
            *(uint*)(g_ohi + g) = ((uint)h1 << 16) | h0;
            *(uint*)(g_olo + g) = ((uint)l1 << 16) | l0;
        }
        if (start >= N_TOT - N_OUT) {
            const int off = start - (N_TOT - N_OUT);
            for (int idx = tid; idx < KB * BT; idx += NTHR) {
                int j = idx % KB, c = idx / KB;
                out[(c0 + c) * N_OUT + off + j] = osm_blk[j * OS_PAD + c];
            }
        }
    }
}

extern "C" void kernel_launch(void* const* d_in, const int* in_sizes, int n_in,
                              void* d_out, int out_size)
{
    const float* x    = (const float*)d_in[0];
    const float* W    = (const float*)d_in[1];
    const float* bias = (const float*)d_in[2];
    float* out        = (float*)d_out;

    convW_kernel<<<(N_EV * N_TOT / 4) / 256, 256>>>(W);

    cudaFuncSetAttribute(neat_ff_kernel,
                         cudaFuncAttributeMaxDynamicSharedMemorySize, SMEM_BYTES);
    neat_ff_kernel<<<NCTA, NTHR, SMEM_BYTES>>>(x, W, bias, out);
}

// round 8
// speedup vs baseline: 4.1003x; 1.1523x over previous
#include <cuda_runtime.h>
#include <cuda_bf16.h>

#define B_TOT 4096
#define N_IN  512
#define N_TOT 2048
#define N_EV  1536
#define N_OUT 256

#define KB    128          // eval nodes per block (GEMM M)
#define NBLK  (N_EV / KB)  // 12
#define SUB   16           // triangle sub-block
#define BT    32           // batch columns per CTA (GEMM N)
#define NCTA  (B_TOT / BT) // 128
#define NTHR  256          // 8 warps
#define CH    128          // K-chunk

#define OS_PAD   36
#define WSEQ_PAD 129
#define WT_STRIDE 272      // bytes per bf16 tile row (17 x 16B -> conflict-free)

// tile-buffer internal offsets (relative to buffer base)
#define W_HI  0                       // 128 x 272 = 34816
#define W_LO  34816
#define O_HI  69632                   // 32 x 272 = 8704
#define O_LO  78336
#define TILE_BYTES 87040
// double-buffered tiles + solve arrays
#define ZSM_OFF (2 * TILE_BYTES)              // float [128][36] = 18432
#define OSB_OFF (ZSM_OFF + 18432)
#define BSM_OFF (OSB_OFF + 18432)
#define SMEM_BYTES (BSM_OFF + 512)            // 211456

// global bf16 hi/lo tensors (pre-pass W; running outputs in [batch][node])
__device__ __nv_bfloat16 g_Whi[(size_t)N_EV * N_TOT];
__device__ __nv_bfloat16 g_Wlo[(size_t)N_EV * N_TOT];
__device__ __nv_bfloat16 g_ohi[(size_t)B_TOT * N_TOT];
__device__ __nv_bfloat16 g_olo[(size_t)B_TOT * N_TOT];

typedef unsigned long long ull;
typedef unsigned int uint;
typedef unsigned short ushort;

__device__ __forceinline__ uint smem_u32_of(const void* p) {
    uint a; asm("{ .reg .u64 t; cvta.to.shared.u64 t, %1; cvt.u32.u64 %0, t; }"
                : "=r"(a) : "l"(p)); return a;
}
__device__ __forceinline__ void ldsm_x4(uint* r, uint a) {
    asm volatile("ldmatrix.sync.aligned.m8n8.x4.shared.b16 {%0,%1,%2,%3}, [%4];"
                 : "=r"(r[0]), "=r"(r[1]), "=r"(r[2]), "=r"(r[3]) : "r"(a));
}
__device__ __forceinline__ void mma16816(float* d, const uint* a, const uint* b) {
    asm volatile("mma.sync.aligned.m16n8k16.row.col.f32.bf16.bf16.f32 "
                 "{%0,%1,%2,%3}, {%4,%5,%6,%7}, {%8,%9}, {%0,%1,%2,%3};"
                 : "+f"(d[0]), "+f"(d[1]), "+f"(d[2]), "+f"(d[3])
                 : "r"(a[0]), "r"(a[1]), "r"(a[2]), "r"(a[3]),
                   "r"(b[0]), "r"(b[1]));
}

// ---- cp.async (sm_80+ baseline, legal on plain sm_103 target) ----
__device__ __forceinline__ void cp_async16(uint dst, const void* src) {
    asm volatile("cp.async.cg.shared.global [%0], [%1], 16;"
                 :: "r"(dst), "l"(__cvta_generic_to_global(src)) : "memory");
}
#define CP_COMMIT() asm volatile("cp.async.commit_group;" ::: "memory")
#define CP_WAIT1()  asm volatile("cp.async.wait_group 1;" ::: "memory")
#define CP_WAIT0()  asm volatile("cp.async.wait_group 0;" ::: "memory")

// packed fp32x2 (solve phase)
__device__ __forceinline__ ull pack2(float lo, float hi) {
    ull r; asm("mov.b64 %0, {%1, %2};" : "=l"(r) : "f"(lo), "f"(hi)); return r;
}
__device__ __forceinline__ float2 unpack2(ull v) {
    float2 r; asm("mov.b64 {%0, %1}, %2;" : "=f"(r.x), "=f"(r.y) : "l"(v)); return r;
}
__device__ __forceinline__ void ffma2(ull& d, ull a, ull b) {
    asm("fma.rn.f32x2 %0, %1, %2, %0;" : "+l"(d) : "l"(a), "l"(b));
}
__device__ __forceinline__ float fast_sigmoid5(float z) {
    float t = fminf(fmaxf(5.0f * z, -60.0f), 60.0f);
    float e; asm("ex2.approx.f32 %0, %1;" : "=f"(e) : "f"(-t * 1.4426950408889634f));
    float d = 1.0f + e;
    float o; asm("rcp.approx.f32 %0, %1;" : "=f"(o) : "f"(d));
    return o;
}
__device__ __forceinline__ void split_bf16(float v, ushort& h, ushort& l) {
    __nv_bfloat16 hb = __float2bfloat16_rn(v);
    __nv_bfloat16 lb = __float2bfloat16_rn(v - __bfloat162float(hb));
    h = __bfloat16_as_ushort(hb);
    l = __bfloat16_as_ushort(lb);
}

// ---------------- pre-pass: W fp32 -> bf16 hi/lo ----------------
__global__ void convW_kernel(const float* __restrict__ W) {
    int i = blockIdx.x * 256 + threadIdx.x;        // float4 index
    float4 v = ((const float4*)W)[i];
    ushort h0, h1, h2, h3, l0, l1, l2, l3;
    split_bf16(v.x, h0, l0); split_bf16(v.y, h1, l1);
    split_bf16(v.z, h2, l2); split_bf16(v.w, h3, l3);
    ((uint2*)g_Whi)[i] = make_uint2(((uint)h1 << 16) | h0, ((uint)h3 << 16) | h2);
    ((uint2*)g_Wlo)[i] = make_uint2(((uint)l1 << 16) | l0, ((uint)l3 << 16) | l2);
}

extern __shared__ char smemc[];

// stage one 128-K chunk (async): W hi/lo [128][128] + o hi/lo [32][128]
#define STAGE_CHUNK(P0, BUFOFF) do {                                          \
    for (int idx = tid; idx < KB * 16; idx += NTHR) {                         \
        int n = idx >> 4, j8 = idx & 15;                                      \
        size_t g = (size_t)(erow0 + n) * N_TOT + (P0) + j8 * 8;               \
        uint d0 = smem_base + (BUFOFF) + W_HI + n * WT_STRIDE + j8 * 16;      \
        cp_async16(d0, g_Whi + g);                                            \
        cp_async16(d0 + (W_LO - W_HI), g_Wlo + g);                            \
    }                                                                         \
    for (int idx = tid; idx < BT * 16; idx += NTHR) {                         \
        int n = idx >> 4, j8 = idx & 15;                                      \
        size_t g = (size_t)(c0 + n) * N_TOT + (P0) + j8 * 8;                  \
        uint d0 = smem_base + (BUFOFF) + O_HI + n * WT_STRIDE + j8 * 16;      \
        cp_async16(d0, g_ohi + g);                                            \
        cp_async16(d0 + (O_LO - O_HI), g_olo + g);                            \
    }                                                                         \
} while (0)

__global__ __launch_bounds__(NTHR, 1)
void neat_ff_kernel(const float* __restrict__ x,
                    const float* __restrict__ W,
                    const float* __restrict__ bias,
                    float* __restrict__ out)
{
    float* zsm     = (float*)(smemc + ZSM_OFF);
    float* osm_blk = (float*)(smemc + OSB_OFF);
    float* bsm     = (float*)(smemc + BSM_OFF);

    const int  tid = threadIdx.x;
    const int  wid = tid >> 5;
    const int  lid = tid & 31;
    const int  c0  = blockIdx.x * BT;
    const uint smem_base = smem_u32_of(smemc);

    // ---- init: x rows -> g_ohi/g_olo (contiguous, no transpose) ----
    for (int idx = tid; idx < BT * (N_IN / 4); idx += NTHR) {
        int c = idx >> 7, j4 = idx & 127;
        float4 v = *(const float4*)(x + (size_t)(c0 + c) * N_IN + j4 * 4);
        ushort h0, h1, h2, h3, l0, l1, l2, l3;
        split_bf16(v.x, h0, l0); split_bf16(v.y, h1, l1);
        split_bf16(v.z, h2, l2); split_bf16(v.w, h3, l3);
        size_t g = (size_t)(c0 + c) * N_TOT + j4 * 4;
        *(uint2*)(g_ohi + g) = make_uint2(((uint)h1 << 16) | h0, ((uint)h3 << 16) | h2);
        *(uint2*)(g_olo + g) = make_uint2(((uint)l1 << 16) | l0, ((uint)l3 << 16) | l2);
    }
    __syncthreads();

    // per-thread fragment offsets (relative to buffer base)
    const int r0 = wid * 16;                                  // warp's 16 M-rows
    const uint oA = (uint)(r0 + (lid & 15)) * WT_STRIDE + (uint)(lid >> 4) * 16;
    const int  bg = lid >> 3;                                 // 0..3
    const uint oB = (uint)(((bg >> 1) * 8) + (lid & 7)) * WT_STRIDE + (uint)(bg & 1) * 16;

    const int ng  = tid >> 3;   // 0..31 node groups of 4 (solve phase)
    const int cg  = tid & 7;    // 0..7  col groups of 4
    const int ng4 = ng * 4;

    for (int t = 0; t < NBLK; ++t) {
        const int start = N_IN + t * KB;
        const int erow0 = t * KB;

        if (tid < KB) bsm[tid] = bias[erow0 + tid];

        // ================= pipelined HMMA GEMM over previous outputs ==========
        float d[4][4];
        #pragma unroll
        for (int nt = 0; nt < 4; ++nt)
            #pragma unroll
            for (int k = 0; k < 4; ++k) d[nt][k] = 0.0f;

        const int nchunk = start / CH;

        STAGE_CHUNK(0, 0u);            // prologue: chunk 0 -> buf0
        CP_COMMIT();

        for (int ci = 0; ci < nchunk; ++ci) {
            const uint bufoff = (uint)(ci & 1) * TILE_BYTES;
            if (ci + 1 < nchunk) {
                STAGE_CHUNK((ci + 1) * CH, (uint)((ci + 1) & 1) * TILE_BYTES);
                CP_COMMIT();
                CP_WAIT1();            // chunk ci's group complete
            } else {
                CP_WAIT0();
            }
            __syncthreads();           // buf[ci&1] visible to all warps

            const uint aA = smem_base + bufoff + oA;
            const uint aB = smem_base + bufoff + oB;
            #pragma unroll
            for (int kk = 0; kk < 8; ++kk) {
                const uint ko = (uint)kk * 32;
                uint Ah[4], Al[4], Bh0[4], Bh1[4], Bl0[4], Bl1[4];
                ldsm_x4(Ah, aA + W_HI + ko);
                ldsm_x4(Al, aA + W_LO + ko);
                ldsm_x4(Bh0, aB + O_HI + ko);                      // n 0..15
                ldsm_x4(Bh1, aB + O_HI + 16 * WT_STRIDE + ko);     // n 16..31
                ldsm_x4(Bl0, aB + O_LO + ko);
                ldsm_x4(Bl1, aB + O_LO + 16 * WT_STRIDE + ko);
                // 3-pass split: Wh*oh + Wl*oh + Wh*ol
                mma16816(d[0], Ah, Bh0 + 0);  mma16816(d[1], Ah, Bh0 + 2);
                mma16816(d[2], Ah, Bh1 + 0);  mma16816(d[3], Ah, Bh1 + 2);
                mma16816(d[0], Al, Bh0 + 0);  mma16816(d[1], Al, Bh0 + 2);
                mma16816(d[2], Al, Bh1 + 0);  mma16816(d[3], Al, Bh1 + 2);
                mma16816(d[0], Ah, Bl0 + 0);  mma16816(d[1], Ah, Bl0 + 2);
                mma16816(d[2], Ah, Bl1 + 0);  mma16816(d[3], Ah, Bl1 + 2);
            }
            __syncthreads();           // all warps done reading buf[ci&1]
        }

        // ---- write fragments (z pre-bias) into zsm ----
        {
            int rl = r0 + (lid >> 2), cb = (lid & 3) * 2;
            #pragma unroll
            for (int nt = 0; nt < 4; ++nt) {
                *(float2*)&zsm[rl * OS_PAD + nt * 8 + cb]       = make_float2(d[nt][0], d[nt][1]);
                *(float2*)&zsm[(rl + 8) * OS_PAD + nt * 8 + cb] = make_float2(d[nt][2], d[nt][3]);
            }
        }
        __syncthreads();

        // ---- stage in-block fp32 W tile (unions into buffer region; dead now) -
        float* wseq = (float*)smemc;
        for (int idx = tid; idx < KB * KB; idx += NTHR) {
            int n = idx / KB, j = idx % KB;
            wseq[n * WSEQ_PAD + j] = W[(size_t)(erow0 + n) * N_TOT + start + j];
        }
        __syncthreads();

        // ---- load this thread's z tile into packed registers ----
        ull acc2[4][2];
        #pragma unroll
        for (int k = 0; k < 4; ++k) {
            const float* zr = zsm + (ng4 + k) * OS_PAD + cg * 4;
            acc2[k][0] = pack2(zr[0], zr[1]);
            acc2[k][1] = pack2(zr[2], zr[3]);
        }

        // ---- hierarchical sequential solve: 8 x (16-triangle + rank-16) ----
        for (int s = 0; s < 8; ++s) {
            if ((ng >> 2) == s) {
                #pragma unroll
                for (int k = 0; k < 4; ++k)
                    #pragma unroll
                    for (int h = 0; h < 2; ++h) {
                        float2 v = unpack2(acc2[k][h]);
                        zsm[(ng4 + k) * OS_PAD + cg * 4 + 2 * h]     = v.x;
                        zsm[(ng4 + k) * OS_PAD + cg * 4 + 2 * h + 1] = v.y;
                    }
            }
            __syncthreads();

            if (tid < BT) {
                const int col  = tid;
                const int base = s * SUB;
                float oreg[SUB];
                #pragma unroll
                for (int i = 0; i < SUB; ++i) {
                    float z = zsm[(base + i) * OS_PAD + col] + bsm[base + i];
                    #pragma unroll
                    for (int j = 0; j < i; ++j)
                        z += wseq[(base + i) * WSEQ_PAD + (base + j)] * oreg[j];
                    float o = fast_sigmoid5(z);
                    oreg[i] = o;
                    osm_blk[(base + i) * OS_PAD + col] = o;
                }
            }
            __syncthreads();

            if (ng >= 4 * (s + 1)) {
                #pragma unroll
                for (int j = 0; j < SUB; ++j) {
                    int jj = s * SUB + j;
                    const ull* o2 = (const ull*)&osm_blk[jj * OS_PAD + cg * 4];
                    ull o0 = o2[0], o1 = o2[1];
                    #pragma unroll
                    for (int k = 0; k < 4; ++k) {
                        float w = wseq[(ng4 + k) * WSEQ_PAD + jj];
                        ull wp = pack2(w, w);
                        ffma2(acc2[k][0], wp, o0);
                        ffma2(acc2[k][1], wp, o1);
                    }
                }
            }
        }
        __syncthreads();

        // ---- commit block outputs as bf16 hi/lo ([batch][node] layout) ----
        for (int idx = tid; idx < BT * (KB / 2); idx += NTHR) {
            int c = idx >> 6, j2 = idx & 63;
            float o0 = osm_blk[(2 * j2) * OS_PAD + c];
            float o1 = osm_blk[(2 * j2 + 1) * OS_PAD + c];
            ushort h0, h1, l0, l1;
            split_bf16(o0, h0, l0);
            split_bf16(o1, h1, l1);
            size_t g = (size_t)(c0 + c) * N_TOT + start + 2 * j2;
            *(uint*)(g_ohi + g) = ((uint)h1 << 16) | h0;
            *(uint*)(g_olo + g) = ((uint)l1 << 16) | l0;
        }
        if (start >= N_TOT - N_OUT) {
            const int off = start - (N_TOT - N_OUT);
            for (int idx = tid; idx < KB * BT; idx += NTHR) {
                int j = idx % KB, c = idx / KB;
                out[(c0 + c) * N_OUT + off + j] = osm_blk[j * OS_PAD + c];
            }
        }
        __syncthreads();   // commit visible before next block's late-chunk prefetch
    }
}

extern "C" void kernel_launch(void* const* d_in, const int* in_sizes, int n_in,
                              void* d_out, int out_size)
{
    const float* x    = (const float*)d_in[0];
    const float* W    = (const float*)d_in[1];
    const float* bias = (const float*)d_in[2];
    float* out        = (float*)d_out;

    convW_kernel<<<(N_EV * N_TOT / 4) / 256, 256>>>(W);

    cudaFuncSetAttribute(neat_ff_kernel,
                         cudaFuncAttributeMaxDynamicSharedMemorySize, SMEM_BYTES);
    neat_ff_kernel<<<NCTA, NTHR, SMEM_BYTES>>>(x, W, bias, out);
}